// round 4
// baseline (speedup 1.0000x reference)
#include <cuda_runtime.h>
#include <cstdint>

typedef unsigned long long ull;

#define B_TOTAL   131072
#define DIMN      256
#define NLAYERS   6
#define MTILE     64
#define NTHREADS  256

// output layout: h_final [B,256] then aligns[6,B,3], divs[6,B,3], tens[6,B,3]
#define OUT_ALIGN 33554432
#define OUT_DIV   35913728
#define OUT_TEN   38273024

// smem float offsets
#define SM_H   0        // 16384 : h tile [64][256]
#define SM_Z   16384    // 16384 : tanh tile [64][256]
#define SM_W   32768    // 16384 : W staging, 2 buffers x 8192 floats (4096 float2)
#define SM_A   49152    // 768   : normalized anchors [3][256]
#define SM_B1  49920    // 256
#define SM_B2  50176    // 256
#define SM_SS  50432    // 64    : per-row ||h||^2
#define SM_D0  50496    // 64    : per-row <h,a0>
#define SM_D1  50560
#define SM_D2  50624
#define SM_TOTALF 50688
#define SMEM_BYTES (SM_TOTALF * 4)

// W1/W2 pre-transposed to k-pair-major: g_Wt[kk*256 + n] = {W[n][2kk], W[n][2kk+1]}
__device__ __align__(16) float2 g_Wt1[128 * 256];
__device__ __align__(16) float2 g_Wt2[128 * 256];
__device__ __align__(16) float  g_an[3 * 256];

// ---------------------------------------------------------------- helpers
__device__ __forceinline__ void fma2(ull& d, ull a, ull b) {
    asm("fma.rn.f32x2 %0, %1, %2, %0;" : "+l"(d) : "l"(a), "l"(b));
}
__device__ __forceinline__ float pair_sum(ull v) {
    return __uint_as_float((unsigned)v) + __uint_as_float((unsigned)(v >> 32));
}
__device__ __forceinline__ void cp_async16(float* s, const float4* g) {
    unsigned sa = (unsigned)__cvta_generic_to_shared(s);
    asm volatile("cp.async.cg.shared.global [%0], [%1], 16;" :: "r"(sa), "l"(g));
}
__device__ __forceinline__ void cp_commit() { asm volatile("cp.async.commit_group;"); }
template <int N> __device__ __forceinline__ void cp_wait() {
    asm volatile("cp.async.wait_group %0;" :: "n"(N));
}
__device__ __forceinline__ void reduce4(float& a, float& b, float& c, float& d) {
#pragma unroll
    for (int off = 16; off > 0; off >>= 1) {
        a += __shfl_xor_sync(0xffffffffu, a, off);
        b += __shfl_xor_sync(0xffffffffu, b, off);
        c += __shfl_xor_sync(0xffffffffu, c, off);
        d += __shfl_xor_sync(0xffffffffu, d, off);
    }
}

// copy one 32KB chunk (16 kk-pairs x 256 cols of float2) into smem
__device__ __forceinline__ void copy_chunk(float* dst, const float4* src, int tid) {
#pragma unroll
    for (int q = 0; q < 8; q++)
        cp_async16(dst + (tid + 256 * q) * 4, src + tid + 256 * q);
}

// D[m, n] += sum_k A[m, k] * W[n, k]   with k-paired f32x2 accumulators.
// A_s: [64][256] fp32 row-major smem.  Bg4: k-pair-major float2 matrix (as float4*).
__device__ __forceinline__ void gemm64(const float* __restrict__ A_s,
                                       const float4* __restrict__ Bg4,
                                       float* wreg, ull (&acc)[8][8],
                                       int tid, int wy, int tx) {
#pragma unroll
    for (int r = 0; r < 8; r++)
#pragma unroll
        for (int j = 0; j < 8; j++) acc[r][j] = 0ull;

    copy_chunk(wreg, Bg4, tid);
    cp_commit();

#pragma unroll 1
    for (int c = 0; c < 8; c++) {
        if (c < 7) {
            copy_chunk(wreg + ((c + 1) & 1) * 8192, Bg4 + (c + 1) * 2048, tid);
            cp_commit();
            cp_wait<1>();
        } else {
            cp_wait<0>();
        }
        __syncthreads();

        const float* wb = wreg + (c & 1) * 8192;       // float2 region, as floats
        const float* Ab = A_s + wy * 8 * 256 + c * 32; // this warp's 8 rows, chunk k-base
#pragma unroll
        for (int kk = 0; kk < 16; kk++) {
            ull bv[8];
#pragma unroll
            for (int j = 0; j < 8; j++)
                bv[j] = *(const ull*)(wb + 2 * (kk * 256 + tx + 32 * j));
#pragma unroll
            for (int r = 0; r < 8; r++) {
                ull av = *(const ull*)(Ab + r * 256 + 2 * kk);
#pragma unroll
                for (int j = 0; j < 8; j++) fma2(acc[r][j], av, bv[j]);
            }
        }
        __syncthreads();
    }
}

// ---------------------------------------------------------------- prep kernel
__global__ void prep_kernel(const float* __restrict__ W1, const float* __restrict__ W2,
                            const float* __restrict__ anchors) {
    int t = blockIdx.x * blockDim.x + threadIdx.x;
    for (int i = t; i < 128 * 256; i += gridDim.x * blockDim.x) {
        int kk = i >> 8, n = i & 255;
        g_Wt1[i] = make_float2(W1[n * 256 + 2 * kk], W1[n * 256 + 2 * kk + 1]);
        g_Wt2[i] = make_float2(W2[n * 256 + 2 * kk], W2[n * 256 + 2 * kk + 1]);
    }
    if (blockIdx.x == 0 && threadIdx.x < 3) {
        int a = threadIdx.x;
        float ss = 0.f;
        for (int k = 0; k < 256; k++) { float v = anchors[a * 256 + k]; ss += v * v; }
        float inv = 1.f / fmaxf(sqrtf(ss), 1e-12f);
        for (int k = 0; k < 256; k++) g_an[a * 256 + k] = anchors[a * 256 + k] * inv;
    }
}

// ---------------------------------------------------------------- main fused kernel
__global__ void __launch_bounds__(NTHREADS, 1)
collapse_kernel(const float* __restrict__ h0, const float* __restrict__ b1,
                const float* __restrict__ b2, float* __restrict__ out) {
    extern __shared__ float sm[];
    float* h_s  = sm + SM_H;
    float* z_s  = sm + SM_Z;
    float* w_s  = sm + SM_W;
    float* a_s  = sm + SM_A;
    float* b1_s = sm + SM_B1;
    float* b2_s = sm + SM_B2;
    float* stss = sm + SM_SS;
    float* std0 = sm + SM_D0;
    float* std1 = sm + SM_D1;
    float* std2 = sm + SM_D2;

    const int tid  = threadIdx.x;
    const int wy   = tid >> 5;   // warp id = row group (8 rows)
    const int tx   = tid & 31;
    const int row0 = blockIdx.x * MTILE;

    // ---- load h tile, anchors, biases
    {
        const float4* hv = (const float4*)(h0 + (size_t)row0 * DIMN);
        float4* hs = (float4*)h_s;
#pragma unroll
        for (int q = 0; q < 16; q++) hs[tid + 256 * q] = hv[tid + 256 * q];
        if (tid < 192) ((float4*)a_s)[tid] = ((const float4*)g_an)[tid];
        if (tid < 64) ((float4*)b1_s)[tid] = ((const float4*)b1)[tid];
        else if (tid < 128) ((float4*)b2_s)[tid - 64] = ((const float4*)b2)[tid - 64];
    }
    __syncthreads();

    // ---- initial per-row stats: ||h||^2, <h, a_i>
#pragma unroll
    for (int r = 0; r < 8; r++) {
        int m = wy * 8 + r;
        float p0 = 0.f, p1 = 0.f, p2 = 0.f, p3 = 0.f;
#pragma unroll
        for (int j = 0; j < 8; j++) {
            int col = tx + 32 * j;
            float hv = h_s[m * 256 + col];
            p0 += hv * hv;
            p1 += hv * a_s[col];
            p2 += hv * a_s[256 + col];
            p3 += hv * a_s[512 + col];
        }
        reduce4(p0, p1, p2, p3);
        if (tx == 0) { stss[m] = p0; std0[m] = p1; std1[m] = p2; std2[m] = p3; }
    }

    ull acc[8][8];

    for (int l = 0; l < NLAYERS; l++) {
        __syncthreads();  // stats + h_s visible to all

        // ---- traces for this layer (one thread per row)
        if (tid < MTILE) {
            float ss = stss[tid];
            float inv = 1.f / fmaxf(sqrtf(ss), 1e-12f);
            float dts[3] = { std0[tid], std1[tid], std2[tid] };
            size_t base = (size_t)(l * B_TOTAL + row0 + tid) * 3;
#pragma unroll
            for (int a = 0; a < 3; a++) {
                float al = dts[a] * inv;
                float dv = 1.f - al;
                out[OUT_ALIGN + base + a] = al;
                out[OUT_DIV   + base + a] = dv;
                out[OUT_TEN   + base + a] = fabsf(dv);
            }
        }

        // ---- GEMM1: pre = h @ W1^T ; z = tanh(pre + b1)
        gemm64(h_s, (const float4*)g_Wt1, w_s, acc, tid, wy, tx);
#pragma unroll
        for (int r = 0; r < 8; r++) {
            int m = wy * 8 + r;
#pragma unroll
            for (int j = 0; j < 8; j++) {
                int col = tx + 32 * j;
                z_s[m * 256 + col] = tanhf(pair_sum(acc[r][j]) + b1_s[col]);
            }
        }
        __syncthreads();

        // ---- GEMM2: delta = z @ W2^T (+ b2 in epilogue)
        gemm64(z_s, (const float4*)g_Wt2, w_s, acc, tid, wy, tx);

        // ---- epilogue: force + update + clip + stats for next layer
#pragma unroll
        for (int r = 0; r < 8; r++) {
            int m = wy * 8 + r;
            float ss = stss[m], d0 = std0[m], d1 = std1[m], d2 = std2[m];
            float inv = 1.f / fmaxf(sqrtf(ss), 1e-12f);
            float dv0 = 1.f - d0 * inv, dv1 = 1.f - d1 * inv, dv2 = 1.f - d2 * inv;
            float nd0 = sqrtf(fmaxf(ss - 2.f * d0 + 1.f, 0.f));
            float nd1 = sqrtf(fmaxf(ss - 2.f * d1 + 1.f, 0.f));
            float nd2 = sqrtf(fmaxf(ss - 2.f * d2 + 1.f, 0.f));
            float ca0 = 0.1f * dv0 / fmaxf(nd0, 1e-12f);
            float ca1 = 0.1f * dv1 / fmaxf(nd1, 1e-12f);
            float ca2 = 0.1f * dv2 / fmaxf(nd2, 1e-12f);
            float hmul = 1.f - (ca0 + ca1 + ca2);

            float v[8];
            float p0 = 0.f, p1 = 0.f, p2 = 0.f, p3 = 0.f;
#pragma unroll
            for (int j = 0; j < 8; j++) {
                int col = tx + 32 * j;
                float hv = h_s[m * 256 + col];
                float dl = pair_sum(acc[r][j]) + b2_s[col];
                float a0 = a_s[col], a1 = a_s[256 + col], a2 = a_s[512 + col];
                float x = hv * hmul + dl + ca0 * a0 + ca1 * a1 + ca2 * a2;
                v[j] = x;
                p0 += x * x; p1 += x * a0; p2 += x * a1; p3 += x * a2;
            }
            reduce4(p0, p1, p2, p3);
            float n = sqrtf(p0);
            float s = (n > 10.f) ? (10.f / (n + 1e-8f)) : 1.f;
#pragma unroll
            for (int j = 0; j < 8; j++) h_s[m * 256 + tx + 32 * j] = v[j] * s;
            if (tx == 0) {
                stss[m] = p0 * s * s;
                std0[m] = p1 * s; std1[m] = p2 * s; std2[m] = p3 * s;
            }
        }
    }
    __syncthreads();

    // ---- store h_final
    {
        float4* ov = (float4*)(out + (size_t)row0 * DIMN);
        const float4* hs = (const float4*)h_s;
#pragma unroll
        for (int q = 0; q < 16; q++) ov[tid + 256 * q] = hs[tid + 256 * q];
    }
}

// ---------------------------------------------------------------- launch
extern "C" void kernel_launch(void* const* d_in, const int* in_sizes, int n_in,
                              void* d_out, int out_size) {
    const float* h0      = (const float*)d_in[0];
    const float* W1      = (const float*)d_in[1];
    const float* b1      = (const float*)d_in[2];
    const float* W2      = (const float*)d_in[3];
    const float* b2      = (const float*)d_in[4];
    const float* anchors = (const float*)d_in[5];
    float* out = (float*)d_out;

    (void)in_sizes; (void)n_in; (void)out_size;

    cudaFuncSetAttribute(collapse_kernel,
                         cudaFuncAttributeMaxDynamicSharedMemorySize, SMEM_BYTES);

    prep_kernel<<<64, 256>>>(W1, W2, anchors);
    collapse_kernel<<<B_TOTAL / MTILE, NTHREADS, SMEM_BYTES>>>(h0, b1, b2, out);
}